// round 17
// baseline (speedup 1.0000x reference)
#include <cuda_runtime.h>
#include <cuda_fp16.h>
#include <math.h>
#include <float.h>
#include <stdint.h>

// Problem constants (fixed shapes from reference setup_inputs)
#define NIMG 2
#define MBOX 1000
#define NBOX (NIMG*MBOX)
#define CCH  256
#define RR   7
#define FCIN (CCH*RR*RR)      // 12544
#define FCIN2 (FCIN/2)        // 6272 k-pair words
#define FCD  1024
#define FCD2 (FCD/2)          // 512
#define SORT_N 1024
#define NWORDS 16             // ceil(1000/64)
#define SCORE_THRESH 0.05f
#define NMS_THRESH 0.5f
#define TOPK 100
#define SCALE_CLAMP 4.135166556742356f  // log(1000/16)

// ---------------- scratch (device globals; no allocations allowed) ----------
// pre-split k-pair-packed fp16 hi/lo (word = half2(x[2k], x[2k+1]))
__device__ uint32_t g_XH[NBOX * FCIN2], g_XL[NBOX * FCIN2];
__device__ uint32_t g_W1H[FCIN2 * FCD], g_W1L[FCIN2 * FCD];
__device__ uint32_t g_W2H[FCD2 * FCD],  g_W2L[FCD2 * FCD];
__device__ uint32_t g_Y1H[NBOX * FCD2], g_Y1L[NBOX * FCD2];
__device__ float g_Y2[NBOX * FCD];
__device__ float g_scores[NBOX];
__device__ float g_pboxes[NBOX * 4];
__device__ unsigned long long g_sup[NIMG * MBOX * NWORDS];

// ---- fp16 scaled split: hi = fp16(x), lo' = fp16((x-hi)*2048) --------------
__device__ __forceinline__ uint32_t split_pair(float x0, float x1, uint32_t& mix) {
    __half h0 = __float2half_rn(x0), h1 = __float2half_rn(x1);
    float r0 = __fmul_rn(__fsub_rn(x0, __half2float(h0)), 2048.0f);
    float r1 = __fmul_rn(__fsub_rn(x1, __half2float(h1)), 2048.0f);
    __half2 m2 = __halves2half2(__float2half_rn(r0), __float2half_rn(r1));
    mix = *(uint32_t*)&m2;
    __half2 h2 = __halves2half2(h0, h1);
    return *(uint32_t*)&h2;
}

// ---------------- weight pre-split (once per launch; ~25us) -----------------
__global__ void wsplit_kernel(const float* __restrict__ W,
                              uint32_t* __restrict__ WH, uint32_t* __restrict__ WL,
                              int K2, int N)
{
    int i = blockIdx.x * blockDim.x + threadIdx.x;
    if (i >= K2 * N) return;
    int k2 = i / N, n = i - k2 * N;
    float x0 = W[(size_t)(2 * k2) * N + n];
    float x1 = W[(size_t)(2 * k2 + 1) * N + n];
    uint32_t lo;
    uint32_t hi = split_pair(x0, x1, lo);
    WH[i] = hi;
    WL[i] = lo;
}

// ---------------- pooling: gather + split directly to g_XH/g_XL -------------
__global__ void pool_kernel(const float* __restrict__ p2, const float* __restrict__ p3,
                            const float* __restrict__ p4, const float* __restrict__ p5,
                            const float* __restrict__ props)
{
    int box = blockIdx.x;           // 0..1999
    int img = box / MBOX;

    __shared__ int soff[49];
    __shared__ const float* sbase;
    __shared__ int sHW;

    if (threadIdx.x == 0) {
        const float* fmaps[4] = {p2, p3, p4, p5};
        const int   Hs[4] = {200, 100, 50, 25};
        const int   Ws[4] = {304, 152, 76, 38};
        const float sc4[4] = {0.25f, 0.125f, 0.0625f, 0.03125f};

        const float* pr = props + (size_t)box * 4;
        float x1o = pr[0], y1o = pr[1], x2o = pr[2], y2o = pr[3];

        float w = __fsub_rn(x2o, x1o);
        float h = __fsub_rn(y2o, y1o);
        float s = sqrtf(fmaxf(__fmul_rn(w, h), 1e-6f));
        float lv = floorf(__fadd_rn(4.0f, log2f(__fadd_rn(__fdiv_rn(s, 224.0f), 1e-8f))));
        lv = fminf(fmaxf(lv, 2.0f), 5.0f);
        int lvl = (int)lv - 2;      // 0..3

        float sc = sc4[lvl];
        float x1 = __fmul_rn(x1o, sc), y1 = __fmul_rn(y1o, sc);
        float x2 = __fmul_rn(x2o, sc), y2 = __fmul_rn(y2o, sc);
        float bw = __fdiv_rn(fmaxf(__fsub_rn(x2, x1), 1.0f), 7.0f);
        float bh = __fdiv_rn(fmaxf(__fsub_rn(y2, y1), 1.0f), 7.0f);
        int Wl = Ws[lvl], Hl = Hs[lvl];
        int six[RR], siy[RR];
        for (int j = 0; j < RR; j++) {
            float cs = (float)j + 0.5f;
            float gx = __fadd_rn(x1, __fmul_rn(cs, bw));
            float gy = __fadd_rn(y1, __fmul_rn(cs, bh));
            six[j] = min(max((int)gx, 0), Wl - 1);
            siy[j] = min(max((int)gy, 0), Hl - 1);
        }
        for (int p = 0; p < 49; p++)
            soff[p] = siy[p / 7] * Wl + six[p % 7];
        sbase = fmaps[lvl] + (size_t)img * CCH * Hl * Wl;
        sHW = Hl * Wl;
    }
    __syncthreads();

    const float* base = sbase;
    int HW = sHW;
    uint32_t* outH = g_XH + (size_t)box * FCIN2;
    uint32_t* outL = g_XL + (size_t)box * FCIN2;
    for (int gidx = threadIdx.x; gidx < FCIN / 4; gidx += blockDim.x) {
        int e = gidx * 4;
        int c = e / 49;
        int p = e - c * 49;
        float vp[4];
        const float* bc_ = base + (size_t)c * HW;
        #pragma unroll
        for (int j = 0; j < 4; j++) {
            vp[j] = __ldg(bc_ + soff[p]);
            if (++p == 49) { p = 0; bc_ += HW; }
        }
        uint32_t l0, l1;
        uint32_t h0 = split_pair(vp[0], vp[1], l0);
        uint32_t h1 = split_pair(vp[2], vp[3], l1);
        *(uint2*)(outH + e / 2) = make_uint2(h0, h1);
        *(uint2*)(outL + e / 2) = make_uint2(l0, l1);
    }
}

// ---------------- fp16x3 tensor GEMM on pre-split operands ------------------
// C = relu(A @ B + bias); A/B given as k-pair-packed fp16 hi/lo word arrays.
// Inner loop: pure loads -> smem -> mma -> fold (no cvt math).
// 128m x 64n per CTA, 256 threads, __launch_bounds__(256,3) for 3 CTAs/SM.
// chh += hiA*hiB; cmix += hiA*lo'B + lo'A*hiB; fold every 4 tiles (64 k):
// y = fma(cmix, 2^-11, chh); fast2sum into master s. Bitwise == R16.
// OUT_SPLIT: emit C as pre-split hi/lo words (for Y1 -> GEMM2 input).
__device__ __forceinline__ void mma_f16(float* c, const uint32_t* a,
                                        uint32_t b0, uint32_t b1) {
    asm volatile(
        "mma.sync.aligned.m16n8k16.row.col.f32.f16.f16.f32 "
        "{%0,%1,%2,%3},{%4,%5,%6,%7},{%8,%9},{%0,%1,%2,%3};\n"
        : "+f"(c[0]), "+f"(c[1]), "+f"(c[2]), "+f"(c[3])
        : "r"(a[0]), "r"(a[1]), "r"(a[2]), "r"(a[3]), "r"(b0), "r"(b1));
}

template<bool RELU, bool OUT_SPLIT>
__global__ void __launch_bounds__(256, 3) tcgemm_kernel(
    const uint32_t* __restrict__ AHp, const uint32_t* __restrict__ ALp,
    const uint32_t* __restrict__ BHp, const uint32_t* __restrict__ BLp,
    const float* __restrict__ bias,
    float* __restrict__ Cf, uint32_t* __restrict__ CH, uint32_t* __restrict__ CL,
    int Mrows, int Kdim, int Ndim)
{
    const int BM = 128, BN = 64, BK = 16;
    const int PA = 132;   // word pitch (128 rows + 4 pad)
    const int PB = 68;
    __shared__ uint32_t Ah[2][8][PA], Am[2][8][PA];
    __shared__ uint32_t Bh[2][8][PB], Bm[2][8][PB];

    int tid = threadIdx.x;
    int lane = tid & 31, wid = tid >> 5;
    int g = lane >> 2, tig = lane & 3;
    int warp_m = (wid & 3) * 32;
    int warp_n = (wid >> 2) * 32;
    int bm = blockIdx.y * BM, bn = blockIdx.x * BN;
    int K2 = Kdim >> 1;

    float s[2][4][4], chh[2][4][4], cmix[2][4][4];
    #pragma unroll
    for (int mt = 0; mt < 2; mt++)
        #pragma unroll
        for (int nt = 0; nt < 4; nt++)
            #pragma unroll
            for (int q = 0; q < 4; q++) {
                s[mt][nt][q] = 0.f; chh[mt][nt][q] = 0.f; cmix[mt][nt][q] = 0.f;
            }

    // fill mapping: A 128 rows x 8 k2-words (uint4/thread); B 8 k2-rows x 64n (uint2/thread)
    int am = tid >> 1, ak2 = (tid & 1) * 4;      // word offset 0 or 4
    int bk2 = tid >> 5, bn2 = (tid & 31) * 2;
    int gr = bm + am;
    bool a_ok = (gr < Mrows);
    const uint32_t* AHrow = AHp + (size_t)(a_ok ? gr : 0) * K2 + ak2;
    const uint32_t* ALrow = ALp + (size_t)(a_ok ? gr : 0) * K2 + ak2;
    const uint32_t* BHrow = BHp + (size_t)bk2 * Ndim + bn + bn2;
    const uint32_t* BLrow = BLp + (size_t)bk2 * Ndim + bn + bn2;

    uint4 avh = make_uint4(0,0,0,0), avl = avh;
    uint2 bvh, bvl;
    if (a_ok) { avh = *(const uint4*)(AHrow); avl = *(const uint4*)(ALrow); }
    bvh = *(const uint2*)(BHrow);
    bvl = *(const uint2*)(BLrow);

    // store tile 0
    Ah[0][ak2 + 0][am] = avh.x; Ah[0][ak2 + 1][am] = avh.y;
    Ah[0][ak2 + 2][am] = avh.z; Ah[0][ak2 + 3][am] = avh.w;
    Am[0][ak2 + 0][am] = avl.x; Am[0][ak2 + 1][am] = avl.y;
    Am[0][ak2 + 2][am] = avl.z; Am[0][ak2 + 3][am] = avl.w;
    Bh[0][bk2][bn2 + 0] = bvh.x; Bh[0][bk2][bn2 + 1] = bvh.y;
    Bm[0][bk2][bn2 + 0] = bvl.x; Bm[0][bk2][bn2 + 1] = bvl.y;
    __syncthreads();

    int buf = 0, tile = 0;
    int ntiles = Kdim / BK;
    for (int t = 1; t <= ntiles; t++) {
        // prefetch next tile (t-th) into registers
        if (t < ntiles) {
            int w0 = t * 8;   // k2-word base of tile t
            if (a_ok) {
                avh = *(const uint4*)(AHrow + w0);
                avl = *(const uint4*)(ALrow + w0);
            }
            bvh = *(const uint2*)(BHrow + (size_t)w0 * Ndim);
            bvl = *(const uint2*)(BLrow + (size_t)w0 * Ndim);
        }

        // ---- A fragments up front; B per nt (proven schedule) ----
        uint32_t aH[2][4], aM[2][4];
        #pragma unroll
        for (int mt = 0; mt < 2; mt++) {
            int r0 = warp_m + mt * 16 + g;
            aH[mt][0] = Ah[buf][tig    ][r0    ];
            aH[mt][1] = Ah[buf][tig    ][r0 + 8];
            aH[mt][2] = Ah[buf][tig + 4][r0    ];
            aH[mt][3] = Ah[buf][tig + 4][r0 + 8];
            aM[mt][0] = Am[buf][tig    ][r0    ];
            aM[mt][1] = Am[buf][tig    ][r0 + 8];
            aM[mt][2] = Am[buf][tig + 4][r0    ];
            aM[mt][3] = Am[buf][tig + 4][r0 + 8];
        }
        #pragma unroll
        for (int nt = 0; nt < 4; nt++) {
            int nn = warp_n + nt * 8 + g;
            uint32_t b0h = Bh[buf][tig    ][nn];
            uint32_t b1h = Bh[buf][tig + 4][nn];
            uint32_t b0m = Bm[buf][tig    ][nn];
            uint32_t b1m = Bm[buf][tig + 4][nn];
            #pragma unroll
            for (int mt = 0; mt < 2; mt++) {
                mma_f16(chh[mt][nt],  aH[mt], b0h, b1h);   // hi*hi
                mma_f16(cmix[mt][nt], aH[mt], b0m, b1m);   // hi*lo'
                mma_f16(cmix[mt][nt], aM[mt], b0h, b1h);   // lo'*hi
            }
        }

        // ---- fold every 4 tiles (64 k): combine scales + fast2sum ----
        tile++;
        if ((tile & 3) == 0) {
            #pragma unroll
            for (int mt = 0; mt < 2; mt++)
                #pragma unroll
                for (int nt = 0; nt < 4; nt++)
                    #pragma unroll
                    for (int q = 0; q < 4; q++) {
                        float y = __fmaf_rn(cmix[mt][nt][q], 4.8828125e-4f, chh[mt][nt][q]);
                        float tt = __fadd_rn(s[mt][nt][q], y);
                        chh[mt][nt][q] = __fadd_rn(__fsub_rn(s[mt][nt][q], tt), y);
                        cmix[mt][nt][q] = 0.f;
                        s[mt][nt][q] = tt;
                    }
        }

        // ---- store prefetched tile into other buffer ----
        if (t < ntiles) {
            int nb = buf ^ 1;
            Ah[nb][ak2 + 0][am] = avh.x; Ah[nb][ak2 + 1][am] = avh.y;
            Ah[nb][ak2 + 2][am] = avh.z; Ah[nb][ak2 + 3][am] = avh.w;
            Am[nb][ak2 + 0][am] = avl.x; Am[nb][ak2 + 1][am] = avl.y;
            Am[nb][ak2 + 2][am] = avl.z; Am[nb][ak2 + 3][am] = avl.w;
            Bh[nb][bk2][bn2 + 0] = bvh.x; Bh[nb][bk2][bn2 + 1] = bvh.y;
            Bm[nb][bk2][bn2 + 0] = bvl.x; Bm[nb][bk2][bn2 + 1] = bvl.y;
            __syncthreads();
            buf = nb;
        }
    }

    // ---- epilogue: rows g / g+8, cols 2*tig, 2*tig+1 ----
    int N2 = Ndim >> 1;
    #pragma unroll
    for (int mt = 0; mt < 2; mt++) {
        int r0 = bm + warp_m + mt * 16 + g;
        #pragma unroll
        for (int nt = 0; nt < 4; nt++) {
            int col = bn + warp_n + nt * 8 + tig * 2;
            if (r0 < Mrows) {
                float v0 = __fadd_rn(__fadd_rn(s[mt][nt][0], chh[mt][nt][0]), bias[col]);
                float v1 = __fadd_rn(__fadd_rn(s[mt][nt][1], chh[mt][nt][1]), bias[col + 1]);
                if (RELU) { v0 = fmaxf(v0, 0.f); v1 = fmaxf(v1, 0.f); }
                if (OUT_SPLIT) {
                    uint32_t lo;
                    uint32_t hi = split_pair(v0, v1, lo);
                    CH[(size_t)r0 * N2 + col / 2] = hi;
                    CL[(size_t)r0 * N2 + col / 2] = lo;
                } else {
                    *(float2*)(Cf + (size_t)r0 * Ndim + col) = make_float2(v0, v1);
                }
            }
            if (r0 + 8 < Mrows) {
                float v2 = __fadd_rn(__fadd_rn(s[mt][nt][2], chh[mt][nt][2]), bias[col]);
                float v3 = __fadd_rn(__fadd_rn(s[mt][nt][3], chh[mt][nt][3]), bias[col + 1]);
                if (RELU) { v2 = fmaxf(v2, 0.f); v3 = fmaxf(v3, 0.f); }
                if (OUT_SPLIT) {
                    uint32_t lo;
                    uint32_t hi = split_pair(v2, v3, lo);
                    CH[(size_t)(r0 + 8) * N2 + col / 2] = hi;
                    CL[(size_t)(r0 + 8) * N2 + col / 2] = lo;
                } else {
                    *(float2*)(Cf + (size_t)(r0 + 8) * Ndim + col) = make_float2(v2, v3);
                }
            }
        }
    }
}

// ---------------- heads: cls/box projections + softmax + deltas + clip ------
__global__ void heads_kernel(const float* __restrict__ Y2,
                             const float* __restrict__ Wc, const float* __restrict__ bc,
                             const float* __restrict__ Wb, const float* __restrict__ bb,
                             const float* __restrict__ props,
                             const int* __restrict__ isz,
                             float* __restrict__ scores, float* __restrict__ pboxes)
{
    int box = blockIdx.x;
    const float* x = Y2 + (size_t)box * FCD;

    double a0 = 0., a1 = 0., a2 = 0., a3 = 0., a4 = 0., a5 = 0.;
    for (int k = threadIdx.x; k < FCD; k += blockDim.x) {
        double xv = (double)x[k];
        a0 += xv * (double)Wc[k * 2 + 0];
        a1 += xv * (double)Wc[k * 2 + 1];
        a2 += xv * (double)Wb[k * 4 + 0];
        a3 += xv * (double)Wb[k * 4 + 1];
        a4 += xv * (double)Wb[k * 4 + 2];
        a5 += xv * (double)Wb[k * 4 + 3];
    }
    __shared__ double red[6][128];
    red[0][threadIdx.x] = a0; red[1][threadIdx.x] = a1; red[2][threadIdx.x] = a2;
    red[3][threadIdx.x] = a3; red[4][threadIdx.x] = a4; red[5][threadIdx.x] = a5;
    __syncthreads();
    for (int s = 64; s > 0; s >>= 1) {
        if (threadIdx.x < s)
            #pragma unroll
            for (int j = 0; j < 6; j++)
                red[j][threadIdx.x] += red[j][threadIdx.x + s];
        __syncthreads();
    }
    if (threadIdx.x == 0) {
        float l0 = (float)(red[0][0] + (double)bc[0]);
        float l1 = (float)(red[1][0] + (double)bc[1]);
        float m = fmaxf(l0, l1);
        float e0 = expf(__fsub_rn(l0, m)), e1 = expf(__fsub_rn(l1, m));
        scores[box] = __fdiv_rn(e1, __fadd_rn(e0, e1));

        float dx = (float)(red[2][0] + (double)bb[0]);
        float dy = (float)(red[3][0] + (double)bb[1]);
        float dw = fminf((float)(red[4][0] + (double)bb[2]), SCALE_CLAMP);
        float dh = fminf((float)(red[5][0] + (double)bb[3]), SCALE_CLAMP);

        const float* pr = props + (size_t)box * 4;
        float w = __fsub_rn(pr[2], pr[0]), h = __fsub_rn(pr[3], pr[1]);
        float cx = __fadd_rn(pr[0], __fmul_rn(0.5f, w));
        float cy = __fadd_rn(pr[1], __fmul_rn(0.5f, h));
        float pcx = __fadd_rn(__fmul_rn(dx, w), cx);
        float pcy = __fadd_rn(__fmul_rn(dy, h), cy);
        float pw = __fmul_rn(expf(dw), w);
        float ph = __fmul_rn(expf(dh), h);

        int img = box / MBOX;
        float Hh = (float)isz[img * 2 + 0];
        float Ww = (float)isz[img * 2 + 1];
        float bx1 = fminf(fmaxf(__fsub_rn(pcx, __fmul_rn(0.5f, pw)), 0.f), Ww);
        float by1 = fminf(fmaxf(__fsub_rn(pcy, __fmul_rn(0.5f, ph)), 0.f), Hh);
        float bx2 = fminf(fmaxf(__fadd_rn(pcx, __fmul_rn(0.5f, pw)), 0.f), Ww);
        float by2 = fminf(fmaxf(__fadd_rn(pcy, __fmul_rn(0.5f, ph)), 0.f), Hh);
        pboxes[box * 4 + 0] = bx1;
        pboxes[box * 4 + 1] = by1;
        pboxes[box * 4 + 2] = bx2;
        pboxes[box * 4 + 3] = by2;
    }
}

// ---------------- per-image stable sort + NMS + topk + write outputs --------
__global__ void __launch_bounds__(512) sortnms_kernel(
    const float* __restrict__ scores, const float* __restrict__ pboxes,
    float* __restrict__ out)
{
    int img = blockIdx.x;
    int tid = threadIdx.x;

    __shared__ float key[SORT_N];
    __shared__ int   idx[SORT_N];
    __shared__ float4 sb[MBOX];
    __shared__ float  sarea[MBOX];
    __shared__ unsigned long long keepw[NWORDS];

    for (int i = tid; i < SORT_N; i += 512) {
        if (i < MBOX) { key[i] = scores[img * MBOX + i]; idx[i] = i; }
        else          { key[i] = -FLT_MAX;               idx[i] = i; }
    }
    __syncthreads();

    for (int k = 2; k <= SORT_N; k <<= 1) {
        for (int j = k >> 1; j > 0; j >>= 1) {
            for (int i = tid; i < SORT_N; i += 512) {
                int ixj = i ^ j;
                if (ixj > i) {
                    float ka = key[i], kb = key[ixj];
                    int ia = idx[i], ib = idx[ixj];
                    bool a_before_b = (ka > kb) || (ka == kb && ia < ib);
                    bool up = ((i & k) == 0);
                    bool sw = up ? !a_before_b : a_before_b;
                    if (sw) { key[i] = kb; key[ixj] = ka; idx[i] = ib; idx[ixj] = ia; }
                }
            }
            __syncthreads();
        }
    }

    for (int i = tid; i < MBOX; i += 512) {
        const float* p = pboxes + (size_t)(img * MBOX + idx[i]) * 4;
        float4 b = make_float4(p[0], p[1], p[2], p[3]);
        sb[i] = b;
        sarea[i] = (b.z - b.x) * (b.w - b.y);
    }
    __syncthreads();

    unsigned long long* sup = g_sup + (size_t)img * MBOX * NWORDS;
    for (int t = tid; t < MBOX * NWORDS; t += 512) {
        int i = t / NWORDS, w = t % NWORDS;
        float4 a = sb[i];
        float aa = sarea[i];
        unsigned long long m = 0ull;
        int j0 = w * 64;
        int jend = min(j0 + 64, MBOX);
        for (int j = max(j0, i + 1); j < jend; j++) {
            float4 b = sb[j];
            float lx = fmaxf(a.x, b.x), ly = fmaxf(a.y, b.y);
            float rx = fminf(a.z, b.z), ry = fminf(a.w, b.w);
            float iw = fmaxf(rx - lx, 0.f), ih = fmaxf(ry - ly, 0.f);
            float inter = iw * ih;
            float iou = inter / fmaxf(aa + sarea[j] - inter, 1e-9f);
            if (iou > NMS_THRESH) m |= 1ull << (j - j0);
        }
        sup[t] = m;
    }
    if (tid < NWORDS) {
        unsigned long long m = 0ull;
        for (int jj = 0; jj < 64; jj++) {
            int j = tid * 64 + jj;
            if (j < MBOX && key[j] > SCORE_THRESH) m |= 1ull << jj;
        }
        keepw[tid] = m;
    }
    __syncthreads();

    if (tid < 32) {
        volatile unsigned long long* kw = keepw;
        for (int i = 0; i < MBOX; i++) {
            unsigned long long kwi = kw[i >> 6];
            __syncwarp();
            if ((kwi >> (i & 63)) & 1ull) {
                if (tid < NWORDS)
                    kw[tid] = kw[tid] & ~sup[(size_t)i * NWORDS + tid];
            }
            __syncwarp();
        }
        if (tid == 0) {
            int cnt = 0;
            for (int i = 0; i < MBOX; i++) {
                int w = i >> 6, b = i & 63;
                if ((kw[w] >> b) & 1ull) {
                    cnt++;
                    if (cnt > TOPK) kw[w] = kw[w] & ~(1ull << b);
                }
            }
        }
    }
    __syncthreads();

    float* oB = out;
    float* oS = out + (size_t)NIMG * MBOX * 4;
    float* oK = oS + (size_t)NIMG * MBOX;
    float* oO = oK + (size_t)NIMG * MBOX;
    for (int i = tid; i < MBOX; i += 512) {
        float4 b = sb[i];
        size_t o = (size_t)(img * MBOX + i);
        oB[o * 4 + 0] = b.x;
        oB[o * 4 + 1] = b.y;
        oB[o * 4 + 2] = b.z;
        oB[o * 4 + 3] = b.w;
        oS[o] = key[i];
        int w = i >> 6, bb2 = i & 63;
        oK[o] = ((keepw[w] >> bb2) & 1ull) ? 1.0f : 0.0f;
        oO[o] = (float)idx[i];
    }
}

// ---------------- launcher ---------------------------------------------------
extern "C" void kernel_launch(void* const* d_in, const int* in_sizes, int n_in,
                              void* d_out, int out_size)
{
    const float* p2    = (const float*)d_in[0];
    const float* p3    = (const float*)d_in[1];
    const float* p4    = (const float*)d_in[2];
    const float* p5    = (const float*)d_in[3];
    const float* props = (const float*)d_in[4];
    const int*   isz   = (const int*)  d_in[5];
    const float* W1    = (const float*)d_in[6];
    const float* b1    = (const float*)d_in[7];
    const float* W2    = (const float*)d_in[8];
    const float* b2    = (const float*)d_in[9];
    const float* Wc    = (const float*)d_in[10];
    const float* bc    = (const float*)d_in[11];
    const float* Wb    = (const float*)d_in[12];
    const float* bb    = (const float*)d_in[13];
    float* out = (float*)d_out;

    void *pXH, *pXL, *pW1H, *pW1L, *pW2H, *pW2L, *pY1H, *pY1L, *pY2, *pSc, *pPb;
    cudaGetSymbolAddress(&pXH,  g_XH);
    cudaGetSymbolAddress(&pXL,  g_XL);
    cudaGetSymbolAddress(&pW1H, g_W1H);
    cudaGetSymbolAddress(&pW1L, g_W1L);
    cudaGetSymbolAddress(&pW2H, g_W2H);
    cudaGetSymbolAddress(&pW2L, g_W2L);
    cudaGetSymbolAddress(&pY1H, g_Y1H);
    cudaGetSymbolAddress(&pY1L, g_Y1L);
    cudaGetSymbolAddress(&pY2,  g_Y2);
    cudaGetSymbolAddress(&pSc,  g_scores);
    cudaGetSymbolAddress(&pPb,  g_pboxes);

    // weight pre-split (once per replay; cheap, deterministic)
    wsplit_kernel<<<(FCIN2 * FCD + 255) / 256, 256>>>(W1, (uint32_t*)pW1H, (uint32_t*)pW1L, FCIN2, FCD);
    wsplit_kernel<<<(FCD2 * FCD + 255) / 256, 256>>>(W2, (uint32_t*)pW2H, (uint32_t*)pW2L, FCD2, FCD);

    pool_kernel<<<NBOX, 256>>>(p2, p3, p4, p5, props);

    dim3 g1(FCD / 64, (NBOX + 127) / 128);   // 16 x 16
    tcgemm_kernel<true, true><<<g1, 256>>>(
        (const uint32_t*)pXH, (const uint32_t*)pXL,
        (const uint32_t*)pW1H, (const uint32_t*)pW1L,
        b1, nullptr, (uint32_t*)pY1H, (uint32_t*)pY1L, NBOX, FCIN, FCD);
    tcgemm_kernel<true, false><<<g1, 256>>>(
        (const uint32_t*)pY1H, (const uint32_t*)pY1L,
        (const uint32_t*)pW2H, (const uint32_t*)pW2L,
        b2, (float*)pY2, nullptr, nullptr, NBOX, FCD, FCD);

    heads_kernel<<<NBOX, 128>>>((float*)pY2, Wc, bc, Wb, bb, props, isz,
                                (float*)pSc, (float*)pPb);

    sortnms_kernel<<<NIMG, 512>>>((float*)pSc, (float*)pPb, out);
}